// round 1
// baseline (speedup 1.0000x reference)
#include <cuda_runtime.h>
#include <math.h>
#include <stdint.h>

#define KTOK   77
#define BATCH  256
#define DMODEL 768
#define NPATCH 576

// ---------------- scratch: scores S[b][k][n] (fp32, 45.4 MB) ----------------
__device__ float g_S[(size_t)BATCH * KTOK * NPATCH];

// ---------------- Kernel A: S = A * V^T  (fp32 SIMT GEMM) ----------------
// CTA tile: 80(M, pad of 77) x 96(N), K-chunks of 32, 256 threads, 5x6 micro-tile.
#define BM 80
#define BN 96
#define BK 32
#define TM 5
#define TN 6
#define ASTR 81    // padded strides for conflict-free smem
#define BSTR 98
#define NCHUNK (DMODEL / BK)   // 24

__device__ __forceinline__ void ldg_tiles(const float* __restrict__ text,
                                          const float* __restrict__ vision,
                                          int b, int n0, int d0, int tid,
                                          float4 ra[3], float4 rb[3]) {
#pragma unroll
    for (int it = 0; it < 3; ++it) {
        int q  = tid + it * 256;       // 0..767
        int r  = q >> 3;               // row within tile
        int dp = (q & 7) << 2;         // d offset within chunk
        if (q < 640 && r < KTOK) {     // A tile: 80 rows x 8 float4
            ra[it] = *(const float4*)&text[((size_t)r * BATCH + b) * DMODEL + d0 + dp];
        } else {
            ra[it] = make_float4(0.f, 0.f, 0.f, 0.f);
        }
        // B tile: 96 rows x 8 float4 = 768 exactly (all threads active)
        rb[it] = *(const float4*)&vision[((size_t)(n0 + r) * BATCH + b) * DMODEL + d0 + dp];
    }
}

__device__ __forceinline__ void sts_tiles(float* As, float* Bs, int tid,
                                          const float4 ra[3], const float4 rb[3]) {
#pragma unroll
    for (int it = 0; it < 3; ++it) {
        int q  = tid + it * 256;
        int r  = q >> 3;
        int dp = (q & 7) << 2;
        if (q < 640) {
            As[(dp + 0) * ASTR + r] = ra[it].x;
            As[(dp + 1) * ASTR + r] = ra[it].y;
            As[(dp + 2) * ASTR + r] = ra[it].z;
            As[(dp + 3) * ASTR + r] = ra[it].w;
        }
        Bs[(dp + 0) * BSTR + r] = rb[it].x;
        Bs[(dp + 1) * BSTR + r] = rb[it].y;
        Bs[(dp + 2) * BSTR + r] = rb[it].z;
        Bs[(dp + 3) * BSTR + r] = rb[it].w;
    }
}

__global__ __launch_bounds__(256, 2)
void scores_kernel(const float* __restrict__ text,
                   const float* __restrict__ vision) {
    __shared__ float smem[2 * BK * ASTR + 2 * BK * BSTR];   // 45.8 KB

    const int tid = threadIdx.x;
    const int b   = blockIdx.y;
    const int n0  = blockIdx.x * BN;
    const int mg  = tid >> 4;   // 0..15 -> rows mg + 16*i
    const int ng  = tid & 15;   // 0..15 -> cols ng*6 + j

    float* As = smem;
    float* Bs = smem + 2 * BK * ASTR;

    float acc[TM][TN];
#pragma unroll
    for (int i = 0; i < TM; ++i)
#pragma unroll
        for (int j = 0; j < TN; ++j) acc[i][j] = 0.f;

    float4 ra[3], rb[3];

    ldg_tiles(text, vision, b, n0, 0, tid, ra, rb);
    sts_tiles(As, Bs, tid, ra, rb);
    __syncthreads();

    for (int c = 0; c < NCHUNK; ++c) {
        if (c + 1 < NCHUNK)
            ldg_tiles(text, vision, b, n0, (c + 1) * BK, tid, ra, rb);

        const float* a_s = As + (c & 1) * BK * ASTR;
        const float* b_s = Bs + (c & 1) * BK * BSTR;
#pragma unroll 8
        for (int dd = 0; dd < BK; ++dd) {
            float af[TM], bf[TN];
#pragma unroll
            for (int i = 0; i < TM; ++i) af[i] = a_s[dd * ASTR + mg + 16 * i];
            float2 b0 = *(const float2*)&b_s[dd * BSTR + ng * 6 + 0];
            float2 b1 = *(const float2*)&b_s[dd * BSTR + ng * 6 + 2];
            float2 b2 = *(const float2*)&b_s[dd * BSTR + ng * 6 + 4];
            bf[0] = b0.x; bf[1] = b0.y; bf[2] = b1.x;
            bf[3] = b1.y; bf[4] = b2.x; bf[5] = b2.y;
#pragma unroll
            for (int i = 0; i < TM; ++i)
#pragma unroll
                for (int j = 0; j < TN; ++j)
                    acc[i][j] = fmaf(af[i], bf[j], acc[i][j]);
        }

        if (c + 1 < NCHUNK)
            sts_tiles(As + ((c + 1) & 1) * BK * ASTR,
                      Bs + ((c + 1) & 1) * BK * BSTR, tid, ra, rb);
        __syncthreads();   // also protects the sts into the other buffer next iter
    }

    // Epilogue: stage tile in smem (stride 100 keeps float4 alignment), then
    // fully coalesced rows of 384B to global.
    float* Ss = smem;   // reuse (8000 floats <= 11456)
#pragma unroll
    for (int i = 0; i < TM; ++i)
#pragma unroll
        for (int j = 0; j < TN; ++j)
            Ss[(mg + 16 * i) * 100 + ng * 6 + j] = acc[i][j];
    __syncthreads();

    for (int q = tid; q < KTOK * 24; q += 256) {
        int row = q / 24;
        int c4  = (q % 24) << 2;
        *(float4*)&g_S[((size_t)b * KTOK + row) * NPATCH + n0 + c4] =
            *(const float4*)&Ss[row * 100 + c4];
    }
}

// ---------------- Kernel B: sparse softmax + decode ----------------
// One warp per (b,k) row. Window 2.5 raw-score units below the row max covers
// every softmax term with weight > e^{-35}; candidates (~1.2/row avg) are
// recomputed in exact fp32 (future-proof: kernel A may become approximate),
// then output = sum of weighted vision rows.
#define CWIN 2.5f

__global__ __launch_bounds__(256)
void decode_kernel(const float* __restrict__ text,
                   const float* __restrict__ vision,
                   float* __restrict__ out) {
    __shared__ unsigned short cidx[8][NPATCH];  // 9.2 KB
    __shared__ float          cs[8][NPATCH];    // 18.4 KB
    __shared__ int            cnt[8];

    const int warp = threadIdx.x >> 5;
    const int lane = threadIdx.x & 31;
    const int row  = blockIdx.x * 8 + warp;     // = b*77 + k
    if (row >= KTOK * BATCH) return;
    const int b = row / KTOK;
    const int k = row % KTOK;

    const float* srow = g_S + (size_t)row * NPATCH;

    // 1) row max (keep values in regs for the second pass)
    float sv[18];
    float m = -INFINITY;
#pragma unroll
    for (int i = 0; i < 18; ++i) {
        sv[i] = srow[lane + 32 * i];
        m = fmaxf(m, sv[i]);
    }
#pragma unroll
    for (int o = 16; o; o >>= 1) m = fmaxf(m, __shfl_xor_sync(~0u, m, o));

    // 2) collect candidates within the window
    if (lane == 0) cnt[warp] = 0;
    __syncwarp();
    const float th = m - CWIN;
#pragma unroll
    for (int i = 0; i < 18; ++i) {
        if (sv[i] >= th) {
            int p = atomicAdd(&cnt[warp], 1);
            cidx[warp][p] = (unsigned short)(lane + 32 * i);
        }
    }
    __syncwarp();
    const int c = cnt[warp];

    // 3) exact fp32 dot for each candidate
    const float* trow = text + ((size_t)k * BATCH + b) * DMODEL;
    for (int ci = 0; ci < c; ++ci) {
        const float* vrow = vision + ((size_t)cidx[warp][ci] * BATCH + b) * DMODEL;
        float s = 0.f;
#pragma unroll
        for (int i = 0; i < 6; ++i) {
            int d = (lane + 32 * i) << 2;
            float4 t4 = *(const float4*)&trow[d];
            float4 v4 = *(const float4*)&vrow[d];
            s = fmaf(t4.x, v4.x, s);
            s = fmaf(t4.y, v4.y, s);
            s = fmaf(t4.z, v4.z, s);
            s = fmaf(t4.w, v4.w, s);
        }
#pragma unroll
        for (int o = 16; o; o >>= 1) s += __shfl_xor_sync(~0u, s, o);
        if (lane == 0) cs[warp][ci] = s;
        __syncwarp();
    }

    // 4) softmax over candidates (terms outside window underflow below 1e-15)
    float mx = -INFINITY;
    for (int ci = 0; ci < c; ++ci) mx = fmaxf(mx, cs[warp][ci]);
    float denom = 0.f;
    for (int ci = 0; ci < c; ++ci) denom += expf((cs[warp][ci] - mx) / 0.07f);
    const float inv = 1.f / denom;
    for (int ci = lane; ci < c; ci += 32)
        cs[warp][ci] = expf((cs[warp][ci] - mx) / 0.07f) * inv;
    __syncwarp();

    // 5) decoded row = sum_c w_c * vision[n_c, b, :]
    float4 o4[6];
#pragma unroll
    for (int i = 0; i < 6; ++i) o4[i] = make_float4(0.f, 0.f, 0.f, 0.f);

    for (int ci = 0; ci < c; ++ci) {
        float w = cs[warp][ci];
        if (w < 1e-12f) continue;
        const float* vrow = vision + ((size_t)cidx[warp][ci] * BATCH + b) * DMODEL;
#pragma unroll
        for (int i = 0; i < 6; ++i) {
            int d = (lane + 32 * i) << 2;
            float4 v4 = *(const float4*)&vrow[d];
            o4[i].x = fmaf(w, v4.x, o4[i].x);
            o4[i].y = fmaf(w, v4.y, o4[i].y);
            o4[i].z = fmaf(w, v4.z, o4[i].z);
            o4[i].w = fmaf(w, v4.w, o4[i].w);
        }
    }

    float* orow = out + ((size_t)k * BATCH + b) * DMODEL;
#pragma unroll
    for (int i = 0; i < 6; ++i)
        *(float4*)&orow[(lane + 32 * i) << 2] = o4[i];
}

// ---------------- launch ----------------
extern "C" void kernel_launch(void* const* d_in, const int* in_sizes, int n_in,
                              void* d_out, int out_size) {
    const float* text   = (const float*)d_in[0];
    const float* vision = (const float*)d_in[1];
    float* out          = (float*)d_out;

    dim3 g1(NPATCH / BN, BATCH);         // 6 x 256 CTAs
    scores_kernel<<<g1, 256>>>(text, vision);

    decode_kernel<<<(KTOK * BATCH) / 8, 256>>>(text, vision, out);  // 2464 CTAs
}

// round 3
// speedup vs baseline: 1.7689x; 1.7689x over previous
#include <cuda_runtime.h>
#include <math.h>
#include <stdint.h>

#define KTOK   77
#define BATCH  256
#define DMODEL 768
#define NPATCH 576

// scratch: scores S[b][k][n] fp32 (45.4 MB)
__device__ float g_S[(size_t)BATCH * KTOK * NPATCH];

// ---------------- Kernel A: S = text · visionᵀ via mma.sync tf32 ----------------
// CTA: b = blockIdx.y, n0 = blockIdx.x*96. M=96 (77 padded), N=96, K chunks of 24.
#define BM   96
#define BN   96
#define KC   24
#define STR  28                  // padded smem row stride (words): conflict-free frags
#define NCH  (DMODEL / KC)       // 32
#define ABUF (BM * STR)          // 2688 words
#define BBUF (BN * STR)          // 2688 words
#define BUFW (ABUF + BBUF)       // 5376 words per stage

__device__ __forceinline__ void mma_tf32(float* c, const uint32_t* a, const uint32_t* b) {
    asm volatile(
        "mma.sync.aligned.m16n8k8.row.col.f32.tf32.tf32.f32 "
        "{%0,%1,%2,%3}, {%4,%5,%6,%7}, {%8,%9}, {%0,%1,%2,%3};"
        : "+f"(c[0]), "+f"(c[1]), "+f"(c[2]), "+f"(c[3])
        : "r"(a[0]), "r"(a[1]), "r"(a[2]), "r"(a[3]), "r"(b[0]), "r"(b[1]));
}

// stage loads: 1152 float4 (A: 576, B: 576) over 256 threads
__device__ __forceinline__ void ldg_tiles(const float* __restrict__ text,
                                          const float* __restrict__ vision,
                                          int b, int n0, int d0, int tid, float4 rg[5]) {
#pragma unroll
    for (int it = 0; it < 5; ++it) {
        int q = tid + it * 256;
        if (q < 576) {                      // A tile: 96 rows x 6 float4
            int r = q / 6, cc = (q % 6) * 4;
            int rr = r < KTOK ? r : KTOK - 1;
            rg[it] = *(const float4*)&text[((size_t)rr * BATCH + b) * DMODEL + d0 + cc];
        } else if (q < 1152) {              // B tile: 96 rows x 6 float4
            int q2 = q - 576;
            int r = q2 / 6, cc = (q2 % 6) * 4;
            rg[it] = *(const float4*)&vision[((size_t)(n0 + r) * BATCH + b) * DMODEL + d0 + cc];
        }
    }
}

__device__ __forceinline__ void sts_tiles(float* As, float* Bs, int tid, const float4 rg[5]) {
#pragma unroll
    for (int it = 0; it < 5; ++it) {
        int q = tid + it * 256;
        if (q < 576) {
            int r = q / 6, cc = (q % 6) * 4;
            *(float4*)&As[r * STR + cc] = rg[it];
        } else if (q < 1152) {
            int q2 = q - 576;
            int r = q2 / 6, cc = (q2 % 6) * 4;
            *(float4*)&Bs[r * STR + cc] = rg[it];
        }
    }
}

__global__ __launch_bounds__(256, 2)
void scores_mma_kernel(const float* __restrict__ text,
                       const float* __restrict__ vision) {
    __shared__ float sm[2 * BUFW];          // 43008 B

    const int tid  = threadIdx.x;
    const int wid  = tid >> 5;
    const int lane = tid & 31;
    const int b    = blockIdx.y;
    const int n0   = blockIdx.x * BN;

    const int l4 = lane >> 2;               // 0..7
    const int lm = lane & 3;                // 0..3
    const int mb = (wid >> 2) * 48;         // warp M offset (0 or 48)
    const int nb = (wid & 3) * 24;          // warp N offset (0,24,48,72)

    float acc[3][3][4];
#pragma unroll
    for (int i = 0; i < 3; ++i)
#pragma unroll
        for (int j = 0; j < 3; ++j)
#pragma unroll
            for (int q = 0; q < 4; ++q) acc[i][j][q] = 0.f;

    float4 rg[5];
    ldg_tiles(text, vision, b, n0, 0, tid, rg);
    sts_tiles(sm, sm + ABUF, tid, rg);
    __syncthreads();

    for (int c = 0; c < NCH; ++c) {
        if (c + 1 < NCH)
            ldg_tiles(text, vision, b, n0, (c + 1) * KC, tid, rg);

        const float* As = sm + (c & 1) * BUFW;
        const float* Bs = As + ABUF;

#pragma unroll
        for (int ks = 0; ks < 3; ++ks) {
            const int k0 = ks * 8;
            uint32_t af[3][4], bf[3][2];
#pragma unroll
            for (int mf = 0; mf < 3; ++mf) {
                const uint32_t* p = (const uint32_t*)As + (mb + mf * 16 + l4) * STR + k0 + lm;
                af[mf][0] = p[0];
                af[mf][1] = p[8 * STR];
                af[mf][2] = p[4];
                af[mf][3] = p[8 * STR + 4];
            }
#pragma unroll
            for (int nf = 0; nf < 3; ++nf) {
                const uint32_t* p = (const uint32_t*)Bs + (nb + nf * 8 + l4) * STR + k0 + lm;
                bf[nf][0] = p[0];
                bf[nf][1] = p[4];
            }
#pragma unroll
            for (int mf = 0; mf < 3; ++mf)
#pragma unroll
                for (int nf = 0; nf < 3; ++nf)
                    mma_tf32(acc[mf][nf], af[mf], bf[nf]);
        }

        if (c + 1 < NCH)
            sts_tiles(sm + ((c + 1) & 1) * BUFW,
                      sm + ((c + 1) & 1) * BUFW + ABUF, tid, rg);
        __syncthreads();
    }

    // Epilogue: direct float2 stores (c0,c1)@(m, n), (c2,c3)@(m+8, n)
#pragma unroll
    for (int mf = 0; mf < 3; ++mf) {
        const int m0 = mb + mf * 16 + l4;
#pragma unroll
        for (int nf = 0; nf < 3; ++nf) {
            const int n = n0 + nb + nf * 8 + 2 * lm;
            if (m0 < KTOK) {
                float2 v = make_float2(acc[mf][nf][0], acc[mf][nf][1]);
                *(float2*)&g_S[((size_t)b * KTOK + m0) * NPATCH + n] = v;
            }
            if (m0 + 8 < KTOK) {
                float2 v = make_float2(acc[mf][nf][2], acc[mf][nf][3]);
                *(float2*)&g_S[((size_t)b * KTOK + m0 + 8) * NPATCH + n] = v;
            }
        }
    }
}

// ---------------- Kernel B: sparse softmax + decode ----------------
// Window 3.0: exact-weight cutoff (1.5) + tf32 score-error margin (1.5).
// Candidates recomputed in exact fp32, so output accuracy is fp32-grade.
#define CWIN 3.0f

__global__ __launch_bounds__(256)
void decode_kernel(const float* __restrict__ text,
                   const float* __restrict__ vision,
                   float* __restrict__ out) {
    __shared__ unsigned short cidx[8][NPATCH];
    __shared__ float          cs[8][NPATCH];
    __shared__ int            cnt[8];

    const int warp = threadIdx.x >> 5;
    const int lane = threadIdx.x & 31;
    const int row  = blockIdx.x * 8 + warp;     // = b*77 + k
    if (row >= KTOK * BATCH) return;
    const int b = row / KTOK;
    const int k = row % KTOK;

    const float* srow = g_S + (size_t)row * NPATCH;

    float sv[18];
    float m = -INFINITY;
#pragma unroll
    for (int i = 0; i < 18; ++i) {
        sv[i] = srow[lane + 32 * i];
        m = fmaxf(m, sv[i]);
    }
#pragma unroll
    for (int o = 16; o; o >>= 1) m = fmaxf(m, __shfl_xor_sync(~0u, m, o));

    if (lane == 0) cnt[warp] = 0;
    __syncwarp();
    const float th = m - CWIN;
#pragma unroll
    for (int i = 0; i < 18; ++i) {
        if (sv[i] >= th) {
            int p = atomicAdd(&cnt[warp], 1);
            cidx[warp][p] = (unsigned short)(lane + 32 * i);
        }
    }
    __syncwarp();
    const int c = cnt[warp];

    // exact fp32 dot per candidate
    const float* trow = text + ((size_t)k * BATCH + b) * DMODEL;
    for (int ci = 0; ci < c; ++ci) {
        const float* vrow = vision + ((size_t)cidx[warp][ci] * BATCH + b) * DMODEL;
        float s = 0.f;
#pragma unroll
        for (int i = 0; i < 6; ++i) {
            int d = (lane + 32 * i) << 2;
            float4 t4 = *(const float4*)&trow[d];
            float4 v4 = *(const float4*)&vrow[d];
            s = fmaf(t4.x, v4.x, s);
            s = fmaf(t4.y, v4.y, s);
            s = fmaf(t4.z, v4.z, s);
            s = fmaf(t4.w, v4.w, s);
        }
#pragma unroll
        for (int o = 16; o; o >>= 1) s += __shfl_xor_sync(~0u, s, o);
        if (lane == 0) cs[warp][ci] = s;
        __syncwarp();
    }

    float mx = -INFINITY;
    for (int ci = 0; ci < c; ++ci) mx = fmaxf(mx, cs[warp][ci]);
    float denom = 0.f;
    for (int ci = 0; ci < c; ++ci) denom += expf((cs[warp][ci] - mx) / 0.07f);
    const float inv = 1.f / denom;
    for (int ci = lane; ci < c; ci += 32)
        cs[warp][ci] = expf((cs[warp][ci] - mx) / 0.07f) * inv;
    __syncwarp();

    float4 o4[6];
#pragma unroll
    for (int i = 0; i < 6; ++i) o4[i] = make_float4(0.f, 0.f, 0.f, 0.f);

    for (int ci = 0; ci < c; ++ci) {
        float w = cs[warp][ci];
        if (w < 1e-12f) continue;
        const float* vrow = vision + ((size_t)cidx[warp][ci] * BATCH + b) * DMODEL;
#pragma unroll
        for (int i = 0; i < 6; ++i) {
            int d = (lane + 32 * i) << 2;
            float4 v4 = *(const float4*)&vrow[d];
            o4[i].x = fmaf(w, v4.x, o4[i].x);
            o4[i].y = fmaf(w, v4.y, o4[i].y);
            o4[i].z = fmaf(w, v4.z, o4[i].z);
            o4[i].w = fmaf(w, v4.w, o4[i].w);
        }
    }

    float* orow = out + ((size_t)k * BATCH + b) * DMODEL;
#pragma unroll
    for (int i = 0; i < 6; ++i)
        *(float4*)&orow[(lane + 32 * i) << 2] = o4[i];
}

// ---------------- launch ----------------
extern "C" void kernel_launch(void* const* d_in, const int* in_sizes, int n_in,
                              void* d_out, int out_size) {
    const float* text   = (const float*)d_in[0];
    const float* vision = (const float*)d_in[1];
    float* out          = (float*)d_out;

    dim3 g1(NPATCH / BN, BATCH);                 // 6 x 256 CTAs
    scores_mma_kernel<<<g1, 256>>>(text, vision);

    decode_kernel<<<(KTOK * BATCH) / 8, 256>>>(text, vision, out);
}

// round 4
// speedup vs baseline: 2.3183x; 1.3106x over previous
#include <cuda_runtime.h>
#include <cuda_bf16.h>
#include <math.h>
#include <stdint.h>

#define KTOK   77
#define BATCH  256
#define DMODEL 768
#define NPATCH 576

// scratch: scores S[b][k][n] fp32 (45.4 MB)
__device__ float g_S[(size_t)BATCH * KTOK * NPATCH];

// ---------------- Kernel A: S = text · visionᵀ via mma.sync bf16 m16n8k16 ----------------
// CTA: b = blockIdx.y, n0 = blockIdx.x*192. M=96 (77 padded), N=192, K chunks of 32.
// 8 warps in 2x4, warp tile 48x48 (3 m16 x 6 n8 frags), 2 k16 steps per chunk.
#define BM    96
#define BN    192
#define KC    32
#define NCH   (DMODEL / KC)      // 24
#define STRW  20                 // smem row stride in 4B words (40 bf16): conflict-free
#define AWRD  (BM * STRW)        // 1920 words
#define BWRD  (BN * STRW)        // 3840 words

__device__ __forceinline__ void mma_bf16(float* c, const uint32_t* a, const uint32_t* b) {
    asm volatile(
        "mma.sync.aligned.m16n8k16.row.col.f32.bf16.bf16.f32 "
        "{%0,%1,%2,%3}, {%4,%5,%6,%7}, {%8,%9}, {%0,%1,%2,%3};"
        : "+f"(c[0]), "+f"(c[1]), "+f"(c[2]), "+f"(c[3])
        : "r"(a[0]), "r"(a[1]), "r"(a[2]), "r"(a[3]), "r"(b[0]), "r"(b[1]));
}

__device__ __forceinline__ uint32_t pack_bf2(float x, float y) {
    __nv_bfloat162 h = __floats2bfloat162_rn(x, y);
    return *(uint32_t*)&h;
}

__global__ __launch_bounds__(256, 2)
void scores_mma_kernel(const float* __restrict__ text,
                       const float* __restrict__ vision) {
    __shared__ __align__(16) uint32_t sm[AWRD + BWRD];   // 23 KB

    const int tid  = threadIdx.x;
    const int wid  = tid >> 5;
    const int lane = tid & 31;
    const int b    = blockIdx.y;
    const int n0   = blockIdx.x * BN;

    const int l4 = lane >> 2;               // 0..7 (row group)
    const int lm = lane & 3;                // 0..3 (k word)
    const int mb = (wid >> 2) * 48;         // warp M offset (0,48)
    const int nb = (wid & 3) * 48;          // warp N offset (0,48,96,144)

    uint32_t* As = sm;
    uint32_t* Bs = sm + AWRD;

    float acc[3][6][4];
#pragma unroll
    for (int i = 0; i < 3; ++i)
#pragma unroll
        for (int j = 0; j < 6; ++j)
#pragma unroll
            for (int q = 0; q < 4; ++q) acc[i][j][q] = 0.f;

    for (int c = 0; c < NCH; ++c) {
        const int d0 = c * KC;

        // ---- gather: 2304 float4 (A 768, B 1536) over 256 threads, 9 each ----
        float4 rg[9];
#pragma unroll
        for (int it = 0; it < 9; ++it) {
            int q = tid + it * 256;
            if (q < 768) {                       // A: 96 rows x 8 float4
                int r = q >> 3, f4 = q & 7;
                int rr = r < KTOK ? r : KTOK - 1;
                rg[it] = *(const float4*)&text[((size_t)rr * BATCH + b) * DMODEL + d0 + f4 * 4];
            } else {                             // B: 192 rows x 8 float4
                int q2 = q - 768;
                int r = q2 >> 3, f4 = q2 & 7;
                rg[it] = *(const float4*)&vision[((size_t)(n0 + r) * BATCH + b) * DMODEL + d0 + f4 * 4];
            }
        }
        __syncthreads();        // previous chunk's compute done: buffer reusable

        // ---- convert + store bf16 ----
#pragma unroll
        for (int it = 0; it < 9; ++it) {
            int q = tid + it * 256;
            uint32_t w0 = pack_bf2(rg[it].x, rg[it].y);
            uint32_t w1 = pack_bf2(rg[it].z, rg[it].w);
            if (q < 768) {
                int r = q >> 3, f4 = q & 7;
                uint32_t* p = As + r * STRW + f4 * 2;
                p[0] = w0; p[1] = w1;
            } else {
                int q2 = q - 768;
                int r = q2 >> 3, f4 = q2 & 7;
                uint32_t* p = Bs + r * STRW + f4 * 2;
                p[0] = w0; p[1] = w1;
            }
        }
        __syncthreads();

        // ---- compute: 2 k16 steps x (3 x 6) MMAs ----
#pragma unroll
        for (int ks = 0; ks < 2; ++ks) {
            const int kw = ks * 8;               // k-step offset in words
            uint32_t af[3][4], bf[6][2];
#pragma unroll
            for (int mf = 0; mf < 3; ++mf) {
                const uint32_t* p = As + (mb + mf * 16 + l4) * STRW + kw + lm;
                af[mf][0] = p[0];
                af[mf][1] = p[8 * STRW];
                af[mf][2] = p[4];
                af[mf][3] = p[8 * STRW + 4];
            }
#pragma unroll
            for (int nf = 0; nf < 6; ++nf) {
                const uint32_t* p = Bs + (nb + nf * 8 + l4) * STRW + kw + lm;
                bf[nf][0] = p[0];
                bf[nf][1] = p[4];
            }
#pragma unroll
            for (int mf = 0; mf < 3; ++mf)
#pragma unroll
                for (int nf = 0; nf < 6; ++nf)
                    mma_bf16(acc[mf][nf], af[mf], bf[nf]);
        }
    }
    __syncthreads();

    // ---- epilogue: float2 stores, rows guarded to 77 ----
#pragma unroll
    for (int mf = 0; mf < 3; ++mf) {
        const int m0 = mb + mf * 16 + l4;
#pragma unroll
        for (int nf = 0; nf < 6; ++nf) {
            const int n = n0 + nb + nf * 8 + 2 * lm;
            if (m0 < KTOK) {
                float2 v = make_float2(acc[mf][nf][0], acc[mf][nf][1]);
                *(float2*)&g_S[((size_t)b * KTOK + m0) * NPATCH + n] = v;
            }
            if (m0 + 8 < KTOK) {
                float2 v = make_float2(acc[mf][nf][2], acc[mf][nf][3]);
                *(float2*)&g_S[((size_t)b * KTOK + m0 + 8) * NPATCH + n] = v;
            }
        }
    }
}

// ---------------- Kernel B: sparse softmax + decode ----------------
// Window 3.5: exact-weight cutoff (1.5) + 2x bf16 score-error margin (1.2) + slack.
// Candidates recomputed in exact fp32, so output accuracy is fp32-grade.
#define CWIN 3.5f

__global__ __launch_bounds__(256)
void decode_kernel(const float* __restrict__ text,
                   const float* __restrict__ vision,
                   float* __restrict__ out) {
    __shared__ unsigned short cidx[8][NPATCH];
    __shared__ float          cs[8][NPATCH];
    __shared__ int            cnt[8];

    const int warp = threadIdx.x >> 5;
    const int lane = threadIdx.x & 31;
    const int row  = blockIdx.x * 8 + warp;     // = b*77 + k
    if (row >= KTOK * BATCH) return;
    const int b = row / KTOK;
    const int k = row % KTOK;

    const float* srow = g_S + (size_t)row * NPATCH;

    float sv[18];
    float m = -INFINITY;
#pragma unroll
    for (int i = 0; i < 18; ++i) {
        sv[i] = srow[lane + 32 * i];
        m = fmaxf(m, sv[i]);
    }
#pragma unroll
    for (int o = 16; o; o >>= 1) m = fmaxf(m, __shfl_xor_sync(~0u, m, o));

    if (lane == 0) cnt[warp] = 0;
    __syncwarp();
    const float th = m - CWIN;
#pragma unroll
    for (int i = 0; i < 18; ++i) {
        if (sv[i] >= th) {
            int p = atomicAdd(&cnt[warp], 1);
            cidx[warp][p] = (unsigned short)(lane + 32 * i);
        }
    }
    __syncwarp();
    const int c = cnt[warp];

    // exact fp32 dot per candidate
    const float* trow = text + ((size_t)k * BATCH + b) * DMODEL;
    for (int ci = 0; ci < c; ++ci) {
        const float* vrow = vision + ((size_t)cidx[warp][ci] * BATCH + b) * DMODEL;
        float s = 0.f;
#pragma unroll
        for (int i = 0; i < 6; ++i) {
            int d = (lane + 32 * i) << 2;
            float4 t4 = *(const float4*)&trow[d];
            float4 v4 = *(const float4*)&vrow[d];
            s = fmaf(t4.x, v4.x, s);
            s = fmaf(t4.y, v4.y, s);
            s = fmaf(t4.z, v4.z, s);
            s = fmaf(t4.w, v4.w, s);
        }
#pragma unroll
        for (int o = 16; o; o >>= 1) s += __shfl_xor_sync(~0u, s, o);
        if (lane == 0) cs[warp][ci] = s;
        __syncwarp();
    }

    float mx = -INFINITY;
    for (int ci = 0; ci < c; ++ci) mx = fmaxf(mx, cs[warp][ci]);
    float denom = 0.f;
    for (int ci = 0; ci < c; ++ci) denom += expf((cs[warp][ci] - mx) / 0.07f);
    const float inv = 1.f / denom;
    for (int ci = lane; ci < c; ci += 32)
        cs[warp][ci] = expf((cs[warp][ci] - mx) / 0.07f) * inv;
    __syncwarp();

    float4 o4[6];
#pragma unroll
    for (int i = 0; i < 6; ++i) o4[i] = make_float4(0.f, 0.f, 0.f, 0.f);

    for (int ci = 0; ci < c; ++ci) {
        float w = cs[warp][ci];
        if (w < 1e-12f) continue;
        const float* vrow = vision + ((size_t)cidx[warp][ci] * BATCH + b) * DMODEL;
#pragma unroll
        for (int i = 0; i < 6; ++i) {
            int d = (lane + 32 * i) << 2;
            float4 v4 = *(const float4*)&vrow[d];
            o4[i].x = fmaf(w, v4.x, o4[i].x);
            o4[i].y = fmaf(w, v4.y, o4[i].y);
            o4[i].z = fmaf(w, v4.z, o4[i].z);
            o4[i].w = fmaf(w, v4.w, o4[i].w);
        }
    }

    float* orow = out + ((size_t)k * BATCH + b) * DMODEL;
#pragma unroll
    for (int i = 0; i < 6; ++i)
        *(float4*)&orow[(lane + 32 * i) << 2] = o4[i];
}

// ---------------- launch ----------------
extern "C" void kernel_launch(void* const* d_in, const int* in_sizes, int n_in,
                              void* d_out, int out_size) {
    const float* text   = (const float*)d_in[0];
    const float* vision = (const float*)d_in[1];
    float* out          = (float*)d_out;

    dim3 g1(NPATCH / BN, BATCH);                 // 3 x 256 CTAs
    scores_mma_kernel<<<g1, 256>>>(text, vision);

    decode_kernel<<<(KTOK * BATCH) / 8, 256>>>(text, vision, out);
}